// round 15
// baseline (speedup 1.0000x reference)
#include <cuda_runtime.h>

#define NN 1024
#define HH 128
#define NJB 8           // j-blocks of 128

// Device-global scratch (no allocation allowed)
__device__ float g_agg[NN * HH];          // atomically accumulated aggregate
__device__ float g_gi[NN * 3 * HH];       // gi = agg @ w_ih^T   [1024][384]
__device__ float g_gh[NN * 3 * HH];       // gh = nf  @ w_hh^T   [1024][384]

// ---------------------------------------------------------------------------
// Kernel 1: barrier-free partial aggregation (frozen round-9 core; measured
// ~60us, regs 32, occ 73%, at the ~4.6 TB/s gated-scatter DRAM floor).
// Output via atomicAdd into g_agg (zeroed by captured memset).
// ---------------------------------------------------------------------------
__global__ __launch_bounds__(256) void agg_kernel(
    const float* __restrict__ nf,
    const int*   __restrict__ adj,
    const float* __restrict__ T)
{
    const int ib   = blockIdx.x;
    const int jb   = blockIdx.y;
    const int tid  = threadIdx.x;
    const int lane = tid & 31;
    const int w    = tid >> 5;
    const int i    = ib * 8 + w;

    const float4* nf4 = (const float4*)nf;
    const float4* T4  = (const float4*)T;

    float4 a0 = make_float4(0.f,0.f,0.f,0.f);
    float4 a1 = make_float4(0.f,0.f,0.f,0.f);
    float4 a2 = make_float4(0.f,0.f,0.f,0.f);
    float4 a3 = make_float4(0.f,0.f,0.f,0.f);

    const int* adjrow = adj + (size_t)i * NN + jb * 128;

    #pragma unroll 1
    for (int c = 0; c < 4; c++) {
        const int av = __ldg(&adjrow[c * 32 + lane]);
        unsigned m = __ballot_sync(0xffffffffu, av != 0);
        int tot = __popc(m);

        const int    jbase   = jb * 128 + c * 32;
        const size_t rowbase = (size_t)i * NN + jbase;

        while (tot >= 4) {
            const int j0 = __ffs(m) - 1; m &= m - 1;
            const int j1 = __ffs(m) - 1; m &= m - 1;
            const int j2 = __ffs(m) - 1; m &= m - 1;
            const int j3 = __ffs(m) - 1; m &= m - 1;
            tot -= 4;
            float4 t0 = __ldcs(&T4[(rowbase + j0) * 32 + lane]);
            float4 t1 = __ldcs(&T4[(rowbase + j1) * 32 + lane]);
            float4 t2 = __ldcs(&T4[(rowbase + j2) * 32 + lane]);
            float4 t3 = __ldcs(&T4[(rowbase + j3) * 32 + lane]);
            float4 f0 = __ldg(&nf4[(size_t)(jbase + j0) * 32 + lane]);
            float4 f1 = __ldg(&nf4[(size_t)(jbase + j1) * 32 + lane]);
            float4 f2 = __ldg(&nf4[(size_t)(jbase + j2) * 32 + lane]);
            float4 f3 = __ldg(&nf4[(size_t)(jbase + j3) * 32 + lane]);
            a0.x += f0.x*t0.x; a0.y += f0.y*t0.y; a0.z += f0.z*t0.z; a0.w += f0.w*t0.w;
            a1.x += f1.x*t1.x; a1.y += f1.y*t1.y; a1.z += f1.z*t1.z; a1.w += f1.w*t1.w;
            a2.x += f2.x*t2.x; a2.y += f2.y*t2.y; a2.z += f2.z*t2.z; a2.w += f2.w*t2.w;
            a3.x += f3.x*t3.x; a3.y += f3.y*t3.y; a3.z += f3.z*t3.z; a3.w += f3.w*t3.w;
        }
        while (tot > 0) {
            const int j = __ffs(m) - 1; m &= m - 1; tot--;
            float4 t = __ldcs(&T4[(rowbase + j) * 32 + lane]);
            float4 f = __ldg(&nf4[(size_t)(jbase + j) * 32 + lane]);
            a0.x += f.x*t.x; a0.y += f.y*t.y; a0.z += f.z*t.z; a0.w += f.w*t.w;
        }
    }

    a0.x += a1.x + a2.x + a3.x;
    a0.y += a1.y + a2.y + a3.y;
    a0.z += a1.z + a2.z + a3.z;
    a0.w += a1.w + a2.w + a3.w;

    float* dst = g_agg + (size_t)i * HH + lane * 4;
    atomicAdd(dst + 0, a0.x);
    atomicAdd(dst + 1, a0.y);
    atomicAdd(dst + 2, a0.z);
    atomicAdd(dst + 3, a0.w);
}

// ---------------------------------------------------------------------------
// Kernel 2: tiled GEMM, SINGLE full-K staging phase (67.6 KB dynamic smem).
// C[1024 x 384] = A[1024 x 128] @ W[384 x 128]^T. grid (16, 6), 64x64 tile,
// 4x4 microtile. 16 global loads issued back-to-back (MLP 16), one barrier,
// then a pure 32-step FFMA loop. Staging latency paid once, not twice.
// ---------------------------------------------------------------------------
__global__ __launch_bounds__(256) void gemm64_kernel(
    const float* __restrict__ A,
    const float* __restrict__ W,
    float*       __restrict__ C)
{
    extern __shared__ float4 dsm[];
    float4* sA = dsm;              // [64][33]
    float4* sB = dsm + 64 * 33;    // [64][33]

    const int mt  = blockIdx.x;
    const int nt  = blockIdx.y;
    const int tid = threadIdx.x;
    const int tx  = tid & 15;
    const int ty  = tid >> 4;

    const float4* A4 = (const float4*)A;
    const float4* W4 = (const float4*)W;
    float4*       C4 = (float4*)C;

    const int mbase = mt * 64;
    const int nbase = nt * 64;

    // Stage full K: 2048 float4 each, 8 per thread, all loads independent.
    #pragma unroll
    for (int e = tid; e < 64 * 32; e += 256) {
        const int m = e >> 5, kq = e & 31;
        sA[m * 33 + kq] = A4[(size_t)(mbase + m) * 32 + kq];
    }
    #pragma unroll
    for (int e = tid; e < 64 * 32; e += 256) {
        const int n = e >> 5, kq = e & 31;
        sB[n * 33 + kq] = W4[(size_t)(nbase + n) * 32 + kq];
    }
    __syncthreads();

    float c00=0,c01=0,c02=0,c03=0, c10=0,c11=0,c12=0,c13=0;
    float c20=0,c21=0,c22=0,c23=0, c30=0,c31=0,c32=0,c33=0;

    #pragma unroll 8
    for (int kq = 0; kq < 32; kq++) {
        const float4 a0 = sA[(ty * 4 + 0) * 33 + kq];
        const float4 a1 = sA[(ty * 4 + 1) * 33 + kq];
        const float4 a2 = sA[(ty * 4 + 2) * 33 + kq];
        const float4 a3 = sA[(ty * 4 + 3) * 33 + kq];
        const float4 b0 = sB[(tx * 4 + 0) * 33 + kq];
        const float4 b1 = sB[(tx * 4 + 1) * 33 + kq];
        const float4 b2 = sB[(tx * 4 + 2) * 33 + kq];
        const float4 b3 = sB[(tx * 4 + 3) * 33 + kq];

        c00 += a0.x*b0.x + a0.y*b0.y + a0.z*b0.z + a0.w*b0.w;
        c01 += a0.x*b1.x + a0.y*b1.y + a0.z*b1.z + a0.w*b1.w;
        c02 += a0.x*b2.x + a0.y*b2.y + a0.z*b2.z + a0.w*b2.w;
        c03 += a0.x*b3.x + a0.y*b3.y + a0.z*b3.z + a0.w*b3.w;
        c10 += a1.x*b0.x + a1.y*b0.y + a1.z*b0.z + a1.w*b0.w;
        c11 += a1.x*b1.x + a1.y*b1.y + a1.z*b1.z + a1.w*b1.w;
        c12 += a1.x*b2.x + a1.y*b2.y + a1.z*b2.z + a1.w*b2.w;
        c13 += a1.x*b3.x + a1.y*b3.y + a1.z*b3.z + a1.w*b3.w;
        c20 += a2.x*b0.x + a2.y*b0.y + a2.z*b0.z + a2.w*b0.w;
        c21 += a2.x*b1.x + a2.y*b1.y + a2.z*b1.z + a2.w*b1.w;
        c22 += a2.x*b2.x + a2.y*b2.y + a2.z*b2.z + a2.w*b2.w;
        c23 += a2.x*b3.x + a2.y*b3.y + a2.z*b3.z + a2.w*b3.w;
        c30 += a3.x*b0.x + a3.y*b0.y + a3.z*b0.z + a3.w*b0.w;
        c31 += a3.x*b1.x + a3.y*b1.y + a3.z*b1.z + a3.w*b1.w;
        c32 += a3.x*b2.x + a3.y*b2.y + a3.z*b2.z + a3.w*b2.w;
        c33 += a3.x*b3.x + a3.y*b3.y + a3.z*b3.z + a3.w*b3.w;
    }

    const int m0 = mbase + ty * 4;
    const int n4 = nt * 16 + tx;
    C4[(size_t)(m0 + 0) * 96 + n4] = make_float4(c00, c01, c02, c03);
    C4[(size_t)(m0 + 1) * 96 + n4] = make_float4(c10, c11, c12, c13);
    C4[(size_t)(m0 + 2) * 96 + n4] = make_float4(c20, c21, c22, c23);
    C4[(size_t)(m0 + 3) * 96 + n4] = make_float4(c30, c31, c32, c33);
}

// ---------------------------------------------------------------------------
// Kernel 3: fused GRU epilogue, float4-vectorized (4 h per thread).
// ---------------------------------------------------------------------------
__global__ __launch_bounds__(256) void gru_ep_kernel(
    const float* __restrict__ nf,
    const float* __restrict__ bih,
    const float* __restrict__ bhh,
    float*       __restrict__ out)
{
    const int e  = blockIdx.x * 256 + threadIdx.x;  // f4 index in [NN*32]
    const int i  = e >> 5;
    const int hq = e & 31;

    const float4* gi4 = (const float4*)g_gi;  // row = 96 f4
    const float4* gh4 = (const float4*)g_gh;
    const float4* bi4 = (const float4*)bih;   // 96 f4
    const float4* bh4 = (const float4*)bhh;
    const size_t  row = (size_t)i * 96;

    const float4 ir = gi4[row + hq],      hr = gh4[row + hq];
    const float4 iz = gi4[row + 32 + hq], hz = gh4[row + 32 + hq];
    const float4 in_= gi4[row + 64 + hq], hn = gh4[row + 64 + hq];
    const float4 bir = bi4[hq],      bhr = bh4[hq];
    const float4 biz = bi4[32 + hq], bhz = bh4[32 + hq];
    const float4 bin = bi4[64 + hq], bhn = bh4[64 + hq];
    const float4 hp  = ((const float4*)nf)[e];

    float4 o;
    {
        float r = 1.f / (1.f + __expf(-(ir.x + hr.x + bir.x + bhr.x)));
        float z = 1.f / (1.f + __expf(-(iz.x + hz.x + biz.x + bhz.x)));
        float n = tanhf(in_.x + bin.x + r * (hn.x + bhn.x));
        o.x = (1.f - z) * n + z * hp.x;
    }
    {
        float r = 1.f / (1.f + __expf(-(ir.y + hr.y + bir.y + bhr.y)));
        float z = 1.f / (1.f + __expf(-(iz.y + hz.y + biz.y + bhz.y)));
        float n = tanhf(in_.y + bin.y + r * (hn.y + bhn.y));
        o.y = (1.f - z) * n + z * hp.y;
    }
    {
        float r = 1.f / (1.f + __expf(-(ir.z + hr.z + bir.z + bhr.z)));
        float z = 1.f / (1.f + __expf(-(iz.z + hz.z + biz.z + bhz.z)));
        float n = tanhf(in_.z + bin.z + r * (hn.z + bhn.z));
        o.z = (1.f - z) * n + z * hp.z;
    }
    {
        float r = 1.f / (1.f + __expf(-(ir.w + hr.w + bir.w + bhr.w)));
        float z = 1.f / (1.f + __expf(-(iz.w + hz.w + biz.w + bhz.w)));
        float n = tanhf(in_.w + bin.w + r * (hn.w + bhn.w));
        o.w = (1.f - z) * n + z * hp.w;
    }
    ((float4*)out)[e] = o;
}

extern "C" void kernel_launch(void* const* d_in, const int* in_sizes, int n_in,
                              void* d_out, int out_size)
{
    const float* nf  = (const float*)d_in[0];
    const int*   adj = (const int*)  d_in[1];
    const float* T   = (const float*)d_in[2];
    const float* wih = (const float*)d_in[3];
    const float* whh = (const float*)d_in[4];
    const float* bih = (const float*)d_in[5];
    const float* bhh = (const float*)d_in[6];
    float* out = (float*)d_out;

    float* agg_ptr = nullptr;
    cudaGetSymbolAddress((void**)&agg_ptr, g_agg);
    float* gi_ptr = nullptr;
    cudaGetSymbolAddress((void**)&gi_ptr, g_gi);
    float* gh_ptr = nullptr;
    cudaGetSymbolAddress((void**)&gh_ptr, g_gh);

    const int GEMM_SMEM = 2 * 64 * 33 * (int)sizeof(float4);   // 67.6 KB
    cudaFuncSetAttribute(gemm64_kernel,
                         cudaFuncAttributeMaxDynamicSharedMemorySize, GEMM_SMEM);

    // Fresh fork/join handles each call (host-side only; no device memory).
    cudaStream_t s2;
    cudaEvent_t  ef, ej;
    cudaStreamCreateWithFlags(&s2, cudaStreamNonBlocking);
    cudaEventCreateWithFlags(&ef, cudaEventDisableTiming);
    cudaEventCreateWithFlags(&ej, cudaEventDisableTiming);

    // Main stream: zero the atomic accumulator, then run agg.
    cudaMemsetAsync(agg_ptr, 0, (size_t)NN * HH * sizeof(float), 0);

    // Fork: gh GEMM (independent of agg) runs concurrently on s2.
    cudaEventRecord(ef, 0);
    cudaStreamWaitEvent(s2, ef, 0);
    gemm64_kernel<<<dim3(16, 6), 256, GEMM_SMEM, s2>>>(nf, whh, gh_ptr);

    agg_kernel<<<dim3(NN / 8, NJB), 256>>>(nf, adj, T);

    // Join: gi GEMM needs agg (stream 0); epilogue needs gh (s2) too.
    cudaEventRecord(ej, s2);
    cudaStreamWaitEvent(0, ej, 0);

    gemm64_kernel<<<dim3(16, 6), 256, GEMM_SMEM>>>(agg_ptr, wih, gi_ptr);
    gru_ep_kernel<<<(NN * HH / 4) / 256, 256>>>(nf, bih, bhh, out);
}